// round 15
// baseline (speedup 1.0000x reference)
#include <cuda_runtime.h>
#include <cuda_fp16.h>
#include <cstdint>

#define NN 100000
#define NE 625000
#define DD 128
#define NL 10

// ---------------- scratch (device globals; no allocation allowed) ----------
// packed activations: one uint32 per element = fp16 hi | fp16 lo<<16
static __device__ uint32_t g_pa[(size_t)NN * DD];    // ping
static __device__ uint32_t g_pb[(size_t)NN * DD];    // pong
static __device__ uint32_t g_pagg[(size_t)NN * DD];  // aggregated
// pre-split W smem image: per layer [2 planes][256 k][136 cols (272B rows)]
static __device__ __align__(16) unsigned short g_WT[(size_t)NL * 69632];
static __device__ float g_invdeg[NN];
static __device__ int   g_cnt[NN];
static __device__ int   g_fill[NN];
static __device__ int   g_rowptr[NN + 1];
static __device__ int   g_csr[NE];
static __device__ int   g_bsums[128];

// ---------------- PTX helpers ----------------------------------------------
__device__ __forceinline__ uint32_t smem_u32(const void* p) {
    uint32_t a;
    asm("{ .reg .u64 t; cvta.to.shared.u64 t, %1; cvt.u32.u64 %0, t; }"
        : "=r"(a) : "l"(p));
    return a;
}
__device__ __forceinline__ void ldsm_x4(uint32_t* r, uint32_t addr) {
    asm volatile("ldmatrix.sync.aligned.m8n8.x4.shared.b16 {%0,%1,%2,%3}, [%4];"
                 : "=r"(r[0]), "=r"(r[1]), "=r"(r[2]), "=r"(r[3]) : "r"(addr));
}
__device__ __forceinline__ void ldsm_x4t(uint32_t* r, uint32_t addr) {
    asm volatile("ldmatrix.sync.aligned.m8n8.x4.trans.shared.b16 {%0,%1,%2,%3}, [%4];"
                 : "=r"(r[0]), "=r"(r[1]), "=r"(r[2]), "=r"(r[3]) : "r"(addr));
}
__device__ __forceinline__ void mma_f32(float* d, const uint32_t* a,
                                        uint32_t b0, uint32_t b1) {
    asm volatile(
        "mma.sync.aligned.m16n8k16.row.col.f32.f16.f16.f32 "
        "{%0,%1,%2,%3}, {%4,%5,%6,%7}, {%8,%9}, {%0,%1,%2,%3};"
        : "+f"(d[0]), "+f"(d[1]), "+f"(d[2]), "+f"(d[3])
        : "r"(a[0]), "r"(a[1]), "r"(a[2]), "r"(a[3]), "r"(b0), "r"(b1));
}
__device__ __forceinline__ void mma_f16(uint32_t* d, const uint32_t* a,
                                        uint32_t b0, uint32_t b1) {
    asm volatile(
        "mma.sync.aligned.m16n8k16.row.col.f16.f16.f16.f16 "
        "{%0,%1}, {%2,%3,%4,%5}, {%6,%7}, {%0,%1};"
        : "+r"(d[0]), "+r"(d[1])
        : "r"(a[0]), "r"(a[1]), "r"(a[2]), "r"(a[3]), "r"(b0), "r"(b1));
}

// ---------------- CSR construction -----------------------------------------
__global__ void k_zero(void) {
    int i = blockIdx.x * blockDim.x + threadIdx.x;
    if (i < NN) { g_cnt[i] = 0; g_fill[i] = 0; }
}
__global__ void k_hist(const int* __restrict__ dst) {
    int e = blockIdx.x * blockDim.x + threadIdx.x;
    if (e < NE) atomicAdd(&g_cnt[dst[e]], 1);
}
#define SCAN_B 1024
__global__ void k_scan1(void) {
    __shared__ int sh[SCAN_B];
    int i = blockIdx.x * SCAN_B + threadIdx.x;
    int v = (i < NN) ? g_cnt[i] : 0;
    sh[threadIdx.x] = v;
    __syncthreads();
    for (int off = 1; off < SCAN_B; off <<= 1) {
        int t = (threadIdx.x >= off) ? sh[threadIdx.x - off] : 0;
        __syncthreads();
        sh[threadIdx.x] += t;
        __syncthreads();
    }
    if (i < NN) g_rowptr[i] = sh[threadIdx.x] - v;
    if (threadIdx.x == SCAN_B - 1) g_bsums[blockIdx.x] = sh[threadIdx.x];
}
__global__ void k_scan2(int nb) {
    __shared__ int sh[128];
    int v = (threadIdx.x < nb) ? g_bsums[threadIdx.x] : 0;
    sh[threadIdx.x] = v;
    __syncthreads();
    for (int off = 1; off < 128; off <<= 1) {
        int t = (threadIdx.x >= off) ? sh[threadIdx.x - off] : 0;
        __syncthreads();
        sh[threadIdx.x] += t;
        __syncthreads();
    }
    if (threadIdx.x < nb) g_bsums[threadIdx.x] = sh[threadIdx.x] - v;
}
__global__ void k_scan3(void) {
    int i = blockIdx.x * blockDim.x + threadIdx.x;
    if (i < NN) {
        g_rowptr[i] += g_bsums[i / SCAN_B];
        int c = g_cnt[i];
        g_invdeg[i] = 1.0f / (float)(c > 0 ? c : 1);
    }
    if (i == 0) g_rowptr[NN] = NE;
}
__global__ void k_scatter(const int* __restrict__ src, const int* __restrict__ dst) {
    int e = blockIdx.x * blockDim.x + threadIdx.x;
    if (e >= NE) return;
    int d = dst[e];
    int pos = atomicAdd(&g_fill[d], 1);
    g_csr[g_rowptr[d] + pos] = src[e];
}

// ---------------- fp32 <-> packed split-fp16 --------------------------------
__device__ __forceinline__ uint32_t packsplit(float v) {
    __half hb = __float2half_rn(v);
    float r = v - __half2float(hb);
    __half lb = __float2half_rn(r);
    return (uint32_t)__half_as_ushort(hb) |
           ((uint32_t)__half_as_ushort(lb) << 16);
}
__device__ __forceinline__ float unpacksum(uint32_t p) {
    float2 f = __half22float2(*(__half2*)&p);
    return f.x + f.y;
}

__global__ void k_split(const float* __restrict__ x, uint32_t* __restrict__ xp) {
    size_t i = ((size_t)blockIdx.x * blockDim.x + threadIdx.x) * 4;
    if (i >= (size_t)NN * DD) return;
    float4 v = *(const float4*)(x + i);
    uint4 o;
    o.x = packsplit(v.x); o.y = packsplit(v.y);
    o.z = packsplit(v.z); o.w = packsplit(v.w);
    *(uint4*)(xp + i) = o;
}

__global__ void k_wprep(const float* __restrict__ Wl, const float* __restrict__ Wr) {
    int idx = blockIdx.x * blockDim.x + threadIdx.x;
    if (idx >= NL * 256 * DD) return;
    int l = idx >> 15;
    int rem = idx & 32767;
    int k = rem >> 7;
    int n = rem & 127;
    float w = (k < 128) ? Wl[(size_t)l * 16384 + (size_t)k * 128 + n]
                        : Wr[(size_t)l * 16384 + (size_t)(k - 128) * 128 + n];
    uint32_t p = packsplit(w);
    size_t base = (size_t)l * 69632 + (size_t)k * 136 + n;
    g_WT[base] = (unsigned short)(p & 0xFFFF);
    g_WT[base + 34816] = (unsigned short)(p >> 16);
}

// ---------------- mean aggregation (gather, packed, 4x MLP) ------------------
// one warp per dst node; lane owns 4 packed cols = 1 LDG.128 per edge
__global__ void k_agg(const uint32_t* __restrict__ xp, uint32_t* __restrict__ ap) {
    int node = blockIdx.x * 8 + (threadIdx.x >> 5);
    if (node >= NN) return;
    int lane = threadIdx.x & 31;
    int beg = g_rowptr[node];
    int end = g_rowptr[node + 1];
    float4 acc = make_float4(0.f, 0.f, 0.f, 0.f);
    int t = beg;
    for (; t + 3 < end; t += 4) {
        int s0 = g_csr[t],     s1 = g_csr[t + 1];
        int s2 = g_csr[t + 2], s3 = g_csr[t + 3];
        uint4 v0 = *(const uint4*)(xp + (size_t)s0 * DD + lane * 4);
        uint4 v1 = *(const uint4*)(xp + (size_t)s1 * DD + lane * 4);
        uint4 v2 = *(const uint4*)(xp + (size_t)s2 * DD + lane * 4);
        uint4 v3 = *(const uint4*)(xp + (size_t)s3 * DD + lane * 4);
        acc.x += (unpacksum(v0.x) + unpacksum(v1.x)) +
                 (unpacksum(v2.x) + unpacksum(v3.x));
        acc.y += (unpacksum(v0.y) + unpacksum(v1.y)) +
                 (unpacksum(v2.y) + unpacksum(v3.y));
        acc.z += (unpacksum(v0.z) + unpacksum(v1.z)) +
                 (unpacksum(v2.z) + unpacksum(v3.z));
        acc.w += (unpacksum(v0.w) + unpacksum(v1.w)) +
                 (unpacksum(v2.w) + unpacksum(v3.w));
    }
    for (; t < end; t++) {
        int s0 = g_csr[t];
        uint4 v0 = *(const uint4*)(xp + (size_t)s0 * DD + lane * 4);
        acc.x += unpacksum(v0.x); acc.y += unpacksum(v0.y);
        acc.z += unpacksum(v0.z); acc.w += unpacksum(v0.w);
    }
    float sc = g_invdeg[node];
    uint4 o;
    o.x = packsplit(acc.x * sc); o.y = packsplit(acc.y * sc);
    o.z = packsplit(acc.z * sc); o.w = packsplit(acc.w * sc);
    *(uint4*)(ap + (size_t)node * DD + lane * 4) = o;
}

// ---------------- persistent mma.sync GEMM (512 thr, M=64 tiles) ------------
// Y = [agg|x] @ [Wl;Wr] + b, split-fp16:
//   main AhWh (f32 acc) + corrections AlWh, AhWl (f16 acc).
// Depth-2 register prefetch of A chunks (chunk L+2 issued while computing L).
#define SMEM_W    0
#define W_PLANE   69632
#define SMEM_A    139264
#define A_BUF     9216           // one plane buffer: 64 rows * 144B
#define A_PAIR    18432          // hi+lo pair
#define SMEM_BIAS 176128
#define SMEM_TOT  176640

__global__ __launch_bounds__(512, 1)
void k_gemm_tc(const uint32_t* __restrict__ aggp,
               const uint32_t* __restrict__ curp,
               const unsigned short* __restrict__ wt,
               const float* __restrict__ bias,
               uint32_t* __restrict__ outp,
               float* __restrict__ outf, int last) {
    extern __shared__ char smem[];
    const uint32_t sb = smem_u32(smem);
    const int tid = threadIdx.x;
    const int wid = tid >> 5, lane = tid & 31;
    const int warp_m = wid & 3, warp_n = wid >> 2;   // 4x4

    {   // load W smem image (139264 B = 8704 uint4) + bias
        const uint4* s4 = (const uint4*)wt;
        uint4* d4 = (uint4*)(smem + SMEM_W);
        #pragma unroll
        for (int i = 0; i < 17; i++) d4[tid + i * 512] = s4[tid + i * 512];
        if (tid < 128) ((float*)(smem + SMEM_BIAS))[tid] = bias[tid];
    }
    __syncthreads();

    // ldmatrix bases
    const uint32_t aBase = sb + SMEM_A +
        (uint32_t)(warp_m * 16 + (lane & 15)) * 144 + (uint32_t)(lane >> 4) * 16;
    const uint32_t bBase = sb + SMEM_W +
        (uint32_t)(lane & 15) * 272 +
        (uint32_t)(warp_n * 32 + (lane >> 4) * 8) * 2;

    // loader coords: row = tid/8 (0..63), 8-col slab = (tid&7)*8
    const int ldRow = tid >> 3;
    const int ldC = (tid & 7) * 8;
    const uint32_t stsH = sb + SMEM_A + (uint32_t)ldRow * 144 + (uint32_t)ldC * 2;

    const int nTiles = (NN + 63) / 64;   // 1563

    // depth-2 chunk prefetch: local chunk index L -> tile/chunk mapping
    uint4 pf[2][2];
    #define LOAD_CHUNK(L, DST) do {                                              \
        int _t = (int)blockIdx.x + ((L) >> 2) * (int)gridDim.x;                  \
        int _c = (L) & 3;                                                        \
        if (_t < nTiles) {                                                       \
            const uint32_t* _s = (_c < 2) ? aggp : curp;                         \
            int _row = _t * 64 + ldRow;                                          \
            if (_row < NN) {                                                     \
                const uint4* _p = (const uint4*)(_s + (size_t)_row * DD +        \
                                                 (_c & 1) * 64 + ldC);           \
                (DST)[0] = _p[0]; (DST)[1] = _p[1];                              \
            } else {                                                             \
                (DST)[0] = make_uint4(0, 0, 0, 0);                               \
                (DST)[1] = make_uint4(0, 0, 0, 0);                               \
            }                                                                    \
        }                                                                        \
    } while (0)

    LOAD_CHUNK(0, pf[0]);
    LOAD_CHUNK(1, pf[1]);
    int L = 0;

    for (int tile = blockIdx.x; tile < nTiles; tile += (int)gridDim.x) {
        const int rowBase = tile * 64;
        float acc[4][4];
        uint32_t accC[4][2];
        #pragma unroll
        for (int i = 0; i < 4; i++) {
            #pragma unroll
            for (int j = 0; j < 4; j++) acc[i][j] = 0.f;
            accC[i][0] = 0u; accC[i][1] = 0u;
        }

        #pragma unroll 1
        for (int c = 0; c < 4; c++, L++) {
            const int b = L & 1;
            // split prefetched packed chunk into hi/lo plane buffers
            {
                const uint32_t dH = stsH + (uint32_t)b * A_PAIR;
                const uint32_t dL = dH + A_BUF;
                uint4 q0 = pf[b][0], q1 = pf[b][1];
                uint4 hi, lo;
                hi.x = __byte_perm(q0.x, q0.y, 0x5410);
                hi.y = __byte_perm(q0.z, q0.w, 0x5410);
                hi.z = __byte_perm(q1.x, q1.y, 0x5410);
                hi.w = __byte_perm(q1.z, q1.w, 0x5410);
                lo.x = __byte_perm(q0.x, q0.y, 0x7632);
                lo.y = __byte_perm(q0.z, q0.w, 0x7632);
                lo.z = __byte_perm(q1.x, q1.y, 0x7632);
                lo.w = __byte_perm(q1.z, q1.w, 0x7632);
                asm volatile("st.shared.v4.b32 [%0], {%1,%2,%3,%4};"
                             :: "r"(dH), "r"(hi.x), "r"(hi.y), "r"(hi.z), "r"(hi.w) : "memory");
                asm volatile("st.shared.v4.b32 [%0], {%1,%2,%3,%4};"
                             :: "r"(dL), "r"(lo.x), "r"(lo.y), "r"(lo.z), "r"(lo.w) : "memory");
            }
            // issue load for chunk L+2 into the buffer just consumed
            LOAD_CHUNK(L + 2, pf[b]);
            __syncthreads();

            // compute: main (f32 acc) + corrections (f16 acc)
            const uint32_t aH = aBase + (uint32_t)b * A_PAIR;
            const uint32_t aL = aH + A_BUF;
            const uint32_t wH = bBase + (uint32_t)c * 64 * 272;
            const uint32_t wL = wH + W_PLANE;
            #pragma unroll
            for (int ks = 0; ks < 4; ks++) {
                uint32_t wf[2][4];
                #pragma unroll
                for (int nb = 0; nb < 2; nb++)
                    ldsm_x4t(wf[nb], wH + (uint32_t)ks * 4352 + (uint32_t)nb * 32);
                uint32_t ah[4];
                ldsm_x4(ah, aH + (uint32_t)ks * 32);
                #pragma unroll
                for (int nb = 0; nb < 2; nb++) {
                    mma_f32(acc[nb * 2],     ah, wf[nb][0], wf[nb][1]);
                    mma_f32(acc[nb * 2 + 1], ah, wf[nb][2], wf[nb][3]);
                }
                uint32_t al[4];
                ldsm_x4(al, aL + (uint32_t)ks * 32);
                #pragma unroll
                for (int nb = 0; nb < 2; nb++) {
                    mma_f16(accC[nb * 2],     al, wf[nb][0], wf[nb][1]);
                    mma_f16(accC[nb * 2 + 1], al, wf[nb][2], wf[nb][3]);
                }
                uint32_t wg[2][4];
                #pragma unroll
                for (int nb = 0; nb < 2; nb++)
                    ldsm_x4t(wg[nb], wL + (uint32_t)ks * 4352 + (uint32_t)nb * 32);
                #pragma unroll
                for (int nb = 0; nb < 2; nb++) {
                    mma_f16(accC[nb * 2],     ah, wg[nb][0], wg[nb][1]);
                    mma_f16(accC[nb * 2 + 1], ah, wg[nb][2], wg[nb][3]);
                }
            }
        }

        // ---- epilogue: merge corrections, bias (+relu), store ----
        const float* bs = (const float*)(smem + SMEM_BIAS);
        const int colBase = warp_n * 32 + (lane & 3) * 2;
        const int rBase = rowBase + warp_m * 16 + (lane >> 2);
        #pragma unroll
        for (int j = 0; j < 4; j++) {
            const int col = colBase + j * 8;
            const float b0 = bs[col], b1 = bs[col + 1];
            float2 c0 = __half22float2(*(__half2*)&accC[j][0]); // (r,c),(r,c+1)
            float2 c1 = __half22float2(*(__half2*)&accC[j][1]); // (r+8,c),(r+8,c+1)
            float vv[4];
            vv[0] = acc[j][0] + c0.x + b0;
            vv[1] = acc[j][1] + c0.y + b1;
            vv[2] = acc[j][2] + c1.x + b0;
            vv[3] = acc[j][3] + c1.y + b1;
            #pragma unroll
            for (int rr = 0; rr < 2; rr++) {
                const int row = rBase + rr * 8;
                if (row < NN) {
                    float v0 = vv[rr * 2], v1 = vv[rr * 2 + 1];
                    if (last) {
                        *(float2*)(outf + (size_t)row * DD + col) =
                            make_float2(v0, v1);
                    } else {
                        v0 = fmaxf(v0, 0.f); v1 = fmaxf(v1, 0.f);
                        uint2 o;
                        o.x = packsplit(v0);
                        o.y = packsplit(v1);
                        *(uint2*)(outp + (size_t)row * DD + col) = o;
                    }
                }
            }
        }
    }
    #undef LOAD_CHUNK
}

// ---------------- host driver (graph-capturable) ----------------------------
extern "C" void kernel_launch(void* const* d_in, const int* in_sizes, int n_in,
                              void* d_out, int out_size) {
    const float* x  = (const float*)d_in[0];
    const float* Wl = (const float*)d_in[1];
    const float* Wr = (const float*)d_in[2];
    const float* b  = (const float*)d_in[3];
    const int* ei   = (const int*)d_in[4];
    const int* src  = ei;
    const int* dst  = ei + NE;

    uint32_t *pa, *pb, *pagg;
    unsigned short* wt;
    cudaGetSymbolAddress((void**)&pa, g_pa);
    cudaGetSymbolAddress((void**)&pb, g_pb);
    cudaGetSymbolAddress((void**)&pagg, g_pagg);
    cudaGetSymbolAddress((void**)&wt, g_WT);

    cudaFuncSetAttribute(k_gemm_tc, cudaFuncAttributeMaxDynamicSharedMemorySize, SMEM_TOT);

    const int NB_SCAN = (NN + SCAN_B - 1) / SCAN_B;

    k_zero<<<(NN + 255) / 256, 256>>>();
    k_hist<<<(NE + 255) / 256, 256>>>(dst);
    k_scan1<<<NB_SCAN, SCAN_B>>>();
    k_scan2<<<1, 128>>>(NB_SCAN);
    k_scan3<<<(NN + 255) / 256, 256>>>();
    k_scatter<<<(NE + 255) / 256, 256>>>(src, dst);
    k_split<<<(NN * DD / 4 + 255) / 256, 256>>>(x, pa);
    k_wprep<<<(NL * 256 * DD + 255) / 256, 256>>>(Wl, Wr);

    uint32_t *cur = pa, *nxt = pb;
    for (int i = 0; i < NL; i++) {
        k_agg<<<(NN + 7) / 8, 256>>>(cur, pagg);
        int last = (i == NL - 1) ? 1 : 0;
        k_gemm_tc<<<152, 512, SMEM_TOT>>>(pagg, cur,
                                          wt + (size_t)i * 69632,
                                          b + (size_t)i * DD,
                                          nxt, (float*)d_out, last);
        uint32_t* t = cur; cur = nxt; nxt = t;
    }
}

// round 16
// speedup vs baseline: 1.2325x; 1.2325x over previous
#include <cuda_runtime.h>
#include <cuda_fp16.h>
#include <cstdint>

#define NN 100000
#define NE 625000
#define DD 128
#define NL 10

// ---------------- scratch (device globals; no allocation allowed) ----------
// packed activations: one uint32 per element = fp16 hi | fp16 lo<<16
static __device__ uint32_t g_pa[(size_t)NN * DD];    // ping
static __device__ uint32_t g_pb[(size_t)NN * DD];    // pong
static __device__ uint32_t g_pagg[(size_t)NN * DD];  // aggregated
// pre-split W smem image: per layer [2 planes][256 k][136 cols (272B rows)]
static __device__ __align__(16) unsigned short g_WT[(size_t)NL * 69632];
static __device__ float g_invdeg[NN];
static __device__ int   g_cnt[NN];
static __device__ int   g_fill[NN];
static __device__ int   g_rowptr[NN + 1];
static __device__ int   g_csr[NE];
static __device__ int   g_bsums[128];

// ---------------- PTX helpers ----------------------------------------------
__device__ __forceinline__ uint32_t smem_u32(const void* p) {
    uint32_t a;
    asm("{ .reg .u64 t; cvta.to.shared.u64 t, %1; cvt.u32.u64 %0, t; }"
        : "=r"(a) : "l"(p));
    return a;
}
__device__ __forceinline__ void ldsm_x4(uint32_t* r, uint32_t addr) {
    asm volatile("ldmatrix.sync.aligned.m8n8.x4.shared.b16 {%0,%1,%2,%3}, [%4];"
                 : "=r"(r[0]), "=r"(r[1]), "=r"(r[2]), "=r"(r[3]) : "r"(addr));
}
__device__ __forceinline__ void ldsm_x4t(uint32_t* r, uint32_t addr) {
    asm volatile("ldmatrix.sync.aligned.m8n8.x4.trans.shared.b16 {%0,%1,%2,%3}, [%4];"
                 : "=r"(r[0]), "=r"(r[1]), "=r"(r[2]), "=r"(r[3]) : "r"(addr));
}
// main product: fp16 inputs, fp32 accumulate
__device__ __forceinline__ void mma_f32(float* d, const uint32_t* a,
                                        uint32_t b0, uint32_t b1) {
    asm volatile(
        "mma.sync.aligned.m16n8k16.row.col.f32.f16.f16.f32 "
        "{%0,%1,%2,%3}, {%4,%5,%6,%7}, {%8,%9}, {%0,%1,%2,%3};"
        : "+f"(d[0]), "+f"(d[1]), "+f"(d[2]), "+f"(d[3])
        : "r"(a[0]), "r"(a[1]), "r"(a[2]), "r"(a[3]), "r"(b0), "r"(b1));
}
// correction products: fp16 inputs, fp16 accumulate (2x rate)
__device__ __forceinline__ void mma_f16(uint32_t* d, const uint32_t* a,
                                        uint32_t b0, uint32_t b1) {
    asm volatile(
        "mma.sync.aligned.m16n8k16.row.col.f16.f16.f16.f16 "
        "{%0,%1}, {%2,%3,%4,%5}, {%6,%7}, {%0,%1};"
        : "+r"(d[0]), "+r"(d[1])
        : "r"(a[0]), "r"(a[1]), "r"(a[2]), "r"(a[3]), "r"(b0), "r"(b1));
}

// ---------------- CSR construction -----------------------------------------
__global__ void k_hist(const int* __restrict__ dst) {
    int e = blockIdx.x * blockDim.x + threadIdx.x;
    if (e < NE) atomicAdd(&g_cnt[dst[e]], 1);
}
#define SCAN_B 1024
__global__ void k_scan1(void) {
    __shared__ int sh[SCAN_B];
    int i = blockIdx.x * SCAN_B + threadIdx.x;
    int v = (i < NN) ? g_cnt[i] : 0;
    sh[threadIdx.x] = v;
    __syncthreads();
    for (int off = 1; off < SCAN_B; off <<= 1) {
        int t = (threadIdx.x >= off) ? sh[threadIdx.x - off] : 0;
        __syncthreads();
        sh[threadIdx.x] += t;
        __syncthreads();
    }
    if (i < NN) g_rowptr[i] = sh[threadIdx.x] - v;
    if (threadIdx.x == SCAN_B - 1) g_bsums[blockIdx.x] = sh[threadIdx.x];
}
__global__ void k_scan2(int nb) {
    __shared__ int sh[128];
    int v = (threadIdx.x < nb) ? g_bsums[threadIdx.x] : 0;
    sh[threadIdx.x] = v;
    __syncthreads();
    for (int off = 1; off < 128; off <<= 1) {
        int t = (threadIdx.x >= off) ? sh[threadIdx.x - off] : 0;
        __syncthreads();
        sh[threadIdx.x] += t;
        __syncthreads();
    }
    if (threadIdx.x < nb) g_bsums[threadIdx.x] = sh[threadIdx.x] - v;  // exclusive
}
__global__ void k_scan3(void) {
    int i = blockIdx.x * blockDim.x + threadIdx.x;
    if (i < NN) {
        g_rowptr[i] += g_bsums[i / SCAN_B];
        int c = g_cnt[i];
        g_invdeg[i] = 1.0f / (float)(c > 0 ? c : 1);
    }
    if (i == 0) g_rowptr[NN] = NE;
}
__global__ void k_scatter(const int* __restrict__ src, const int* __restrict__ dst) {
    int e = blockIdx.x * blockDim.x + threadIdx.x;
    if (e >= NE) return;
    int d = dst[e];
    int pos = atomicAdd(&g_fill[d], 1);
    g_csr[g_rowptr[d] + pos] = src[e];
}

// ---------------- fp32 <-> packed split-fp16 --------------------------------
__device__ __forceinline__ uint32_t packsplit(float v) {
    __half hb = __float2half_rn(v);
    float r = v - __half2float(hb);
    __half lb = __float2half_rn(r);
    return (uint32_t)__half_as_ushort(hb) |
           ((uint32_t)__half_as_ushort(lb) << 16);
}
__device__ __forceinline__ float unpacksum(uint32_t p) {
    float2 f = __half22float2(*(__half2*)&p);
    return f.x + f.y;
}

// split input; ALSO zeroes g_cnt/g_fill (runs before k_hist; replaces k_zero)
__global__ void k_split(const float* __restrict__ x, uint32_t* __restrict__ xp) {
    int tidg = blockIdx.x * blockDim.x + threadIdx.x;
    if (tidg < NN) { g_cnt[tidg] = 0; g_fill[tidg] = 0; }
    size_t i = (size_t)tidg * 4;
    if (i >= (size_t)NN * DD) return;
    float4 v = *(const float4*)(x + i);
    uint4 o;
    o.x = packsplit(v.x); o.y = packsplit(v.y);
    o.z = packsplit(v.z); o.w = packsplit(v.w);
    *(uint4*)(xp + i) = o;
}

// ---------------- W pre-split into smem image layout ------------------------
__global__ void k_wprep(const float* __restrict__ Wl, const float* __restrict__ Wr) {
    int idx = blockIdx.x * blockDim.x + threadIdx.x;
    if (idx >= NL * 256 * DD) return;
    int l = idx >> 15;
    int rem = idx & 32767;
    int k = rem >> 7;
    int n = rem & 127;
    float w = (k < 128) ? Wl[(size_t)l * 16384 + (size_t)k * 128 + n]
                        : Wr[(size_t)l * 16384 + (size_t)(k - 128) * 128 + n];
    uint32_t p = packsplit(w);
    size_t base = (size_t)l * 69632 + (size_t)k * 136 + n;
    g_WT[base] = (unsigned short)(p & 0xFFFF);
    g_WT[base + 34816] = (unsigned short)(p >> 16);
}

// ---------------- mean aggregation (gather, packed) -------------------------
// one warp per dst node; lane owns 4 packed cols = 1 LDG.128 per edge
__global__ void k_agg(const uint32_t* __restrict__ xp, uint32_t* __restrict__ ap) {
    int node = blockIdx.x * 8 + (threadIdx.x >> 5);
    if (node >= NN) return;
    int lane = threadIdx.x & 31;
    int beg = g_rowptr[node];
    int end = g_rowptr[node + 1];
    float4 acc = make_float4(0.f, 0.f, 0.f, 0.f);
    int t = beg;
    for (; t + 1 < end; t += 2) {
        int s0 = g_csr[t], s1 = g_csr[t + 1];
        uint4 v0 = *(const uint4*)(xp + (size_t)s0 * DD + lane * 4);
        uint4 v1 = *(const uint4*)(xp + (size_t)s1 * DD + lane * 4);
        acc.x += unpacksum(v0.x) + unpacksum(v1.x);
        acc.y += unpacksum(v0.y) + unpacksum(v1.y);
        acc.z += unpacksum(v0.z) + unpacksum(v1.z);
        acc.w += unpacksum(v0.w) + unpacksum(v1.w);
    }
    if (t < end) {
        int s0 = g_csr[t];
        uint4 v0 = *(const uint4*)(xp + (size_t)s0 * DD + lane * 4);
        acc.x += unpacksum(v0.x); acc.y += unpacksum(v0.y);
        acc.z += unpacksum(v0.z); acc.w += unpacksum(v0.w);
    }
    float sc = g_invdeg[node];
    uint4 o;
    o.x = packsplit(acc.x * sc); o.y = packsplit(acc.y * sc);
    o.z = packsplit(acc.z * sc); o.w = packsplit(acc.w * sc);
    *(uint4*)(ap + (size_t)node * DD + lane * 4) = o;
}

// ---------------- persistent mma.sync GEMM (512 thr, M=64 tiles) ------------
// Y = [agg|x] @ [Wl;Wr] + b, split-fp16:
//   main AhWh (f32 acc) + corrections AlWh, AhWl (f16 acc).
// Warp tile 16x32 (4x4 warp grid over 64x128 block tile).
#define SMEM_W    0
#define W_PLANE   69632
#define SMEM_A    139264
#define A_BUF     9216           // one plane buffer: 64 rows * 144B
#define A_PAIR    18432          // hi+lo pair
#define SMEM_BIAS 176128
#define SMEM_TOT  176640

__global__ __launch_bounds__(512, 1)
void k_gemm_tc(const uint32_t* __restrict__ aggp,
               const uint32_t* __restrict__ curp,
               const unsigned short* __restrict__ wt,
               const float* __restrict__ bias,
               uint32_t* __restrict__ outp,
               float* __restrict__ outf, int last) {
    extern __shared__ char smem[];
    const uint32_t sb = smem_u32(smem);
    const int tid = threadIdx.x;
    const int wid = tid >> 5, lane = tid & 31;
    const int warp_m = wid & 3, warp_n = wid >> 2;   // 4x4

    {   // load W smem image (139264 B = 8704 uint4) + bias
        const uint4* s4 = (const uint4*)wt;
        uint4* d4 = (uint4*)(smem + SMEM_W);
        #pragma unroll
        for (int i = 0; i < 17; i++) d4[tid + i * 512] = s4[tid + i * 512];
        if (tid < 128) ((float*)(smem + SMEM_BIAS))[tid] = bias[tid];
    }
    __syncthreads();

    // ldmatrix bases
    const uint32_t aBase = sb + SMEM_A +
        (uint32_t)(warp_m * 16 + (lane & 15)) * 144 + (uint32_t)(lane >> 4) * 16;
    const uint32_t bBase = sb + SMEM_W +
        (uint32_t)(lane & 15) * 272 +
        (uint32_t)(warp_n * 32 + (lane >> 4) * 8) * 2;

    // loader coords: row = tid/8 (0..63), 8-col slab = (tid&7)*8
    const int ldRow = tid >> 3;
    const int ldC = (tid & 7) * 8;
    const uint32_t stsH = sb + SMEM_A + (uint32_t)ldRow * 144 + (uint32_t)ldC * 2;

    const int nTiles = (NN + 63) / 64;   // 1563
    uint4 pf[2];

    // prologue prefetch: tile(blockIdx), chunk 0 (agg cols 0..63)
    {
        int row = blockIdx.x * 64 + ldRow;
        if ((int)blockIdx.x < nTiles && row < NN) {
            const uint4* p = (const uint4*)(aggp + (size_t)row * DD + ldC);
            pf[0] = p[0]; pf[1] = p[1];
        } else {
            pf[0] = make_uint4(0, 0, 0, 0);
            pf[1] = make_uint4(0, 0, 0, 0);
        }
    }

    for (int tile = blockIdx.x; tile < nTiles; tile += (int)gridDim.x) {
        const int rowBase = tile * 64;
        float acc[4][4];
        uint32_t accC[4][2];
        #pragma unroll
        for (int i = 0; i < 4; i++) {
            #pragma unroll
            for (int j = 0; j < 4; j++) acc[i][j] = 0.f;
            accC[i][0] = 0u; accC[i][1] = 0u;
        }

        #pragma unroll 1
        for (int c = 0; c < 4; c++) {
            const int b = c & 1;
            // split prefetched packed chunk into hi/lo plane buffers
            {
                const uint32_t dH = stsH + (uint32_t)b * A_PAIR;
                const uint32_t dL = dH + A_BUF;
                uint4 q0 = pf[0], q1 = pf[1];
                uint4 hi, lo;
                hi.x = __byte_perm(q0.x, q0.y, 0x5410);
                hi.y = __byte_perm(q0.z, q0.w, 0x5410);
                hi.z = __byte_perm(q1.x, q1.y, 0x5410);
                hi.w = __byte_perm(q1.z, q1.w, 0x5410);
                lo.x = __byte_perm(q0.x, q0.y, 0x7632);
                lo.y = __byte_perm(q0.z, q0.w, 0x7632);
                lo.z = __byte_perm(q1.x, q1.y, 0x7632);
                lo.w = __byte_perm(q1.z, q1.w, 0x7632);
                asm volatile("st.shared.v4.b32 [%0], {%1,%2,%3,%4};"
                             :: "r"(dH), "r"(hi.x), "r"(hi.y), "r"(hi.z), "r"(hi.w) : "memory");
                asm volatile("st.shared.v4.b32 [%0], {%1,%2,%3,%4};"
                             :: "r"(dL), "r"(lo.x), "r"(lo.y), "r"(lo.z), "r"(lo.w) : "memory");
            }
            // prefetch next chunk (or next tile's chunk 0)
            {
                int nt = tile, nc = c + 1;
                if (nc == 4) { nt = tile + (int)gridDim.x; nc = 0; }
                if (nt < nTiles) {
                    const uint32_t* src = (nc < 2) ? aggp : curp;
                    int row = nt * 64 + ldRow;
                    if (row < NN) {
                        const uint4* p = (const uint4*)(src + (size_t)row * DD +
                                                        (nc & 1) * 64 + ldC);
                        pf[0] = p[0]; pf[1] = p[1];
                    } else {
                        pf[0] = make_uint4(0, 0, 0, 0);
                        pf[1] = make_uint4(0, 0, 0, 0);
                    }
                }
            }
            __syncthreads();

            // compute: main (f32 acc) + corrections (f16 acc)
            const uint32_t aH = aBase + (uint32_t)b * A_PAIR;
            const uint32_t aL = aH + A_BUF;
            const uint32_t wH = bBase + (uint32_t)c * 64 * 272;
            const uint32_t wL = wH + W_PLANE;
            #pragma unroll
            for (int ks = 0; ks < 4; ks++) {
                uint32_t wf[2][4];
                #pragma unroll
                for (int nb = 0; nb < 2; nb++)
                    ldsm_x4t(wf[nb], wH + (uint32_t)ks * 4352 + (uint32_t)nb * 32);
                uint32_t ah[4];
                ldsm_x4(ah, aH + (uint32_t)ks * 32);
                #pragma unroll
                for (int nb = 0; nb < 2; nb++) {
                    mma_f32(acc[nb * 2],     ah, wf[nb][0], wf[nb][1]);
                    mma_f32(acc[nb * 2 + 1], ah, wf[nb][2], wf[nb][3]);
                }
                uint32_t al[4];
                ldsm_x4(al, aL + (uint32_t)ks * 32);
                #pragma unroll
                for (int nb = 0; nb < 2; nb++) {
                    mma_f16(accC[nb * 2],     al, wf[nb][0], wf[nb][1]);
                    mma_f16(accC[nb * 2 + 1], al, wf[nb][2], wf[nb][3]);
                }
                uint32_t wg[2][4];
                #pragma unroll
                for (int nb = 0; nb < 2; nb++)
                    ldsm_x4t(wg[nb], wL + (uint32_t)ks * 4352 + (uint32_t)nb * 32);
                #pragma unroll
                for (int nb = 0; nb < 2; nb++) {
                    mma_f16(accC[nb * 2],     ah, wg[nb][0], wg[nb][1]);
                    mma_f16(accC[nb * 2 + 1], ah, wg[nb][2], wg[nb][3]);
                }
            }
        }

        // ---- epilogue: merge corrections, bias (+relu), store ----
        const float* bs = (const float*)(smem + SMEM_BIAS);
        const int colBase = warp_n * 32 + (lane & 3) * 2;
        const int rBase = rowBase + warp_m * 16 + (lane >> 2);
        #pragma unroll
        for (int j = 0; j < 4; j++) {
            const int col = colBase + j * 8;
            const float b0 = bs[col], b1 = bs[col + 1];
            float2 c0 = __half22float2(*(__half2*)&accC[j][0]); // (r,c),(r,c+1)
            float2 c1 = __half22float2(*(__half2*)&accC[j][1]); // (r+8,c),(r+8,c+1)
            float vv[4];
            vv[0] = acc[j][0] + c0.x + b0;
            vv[1] = acc[j][1] + c0.y + b1;
            vv[2] = acc[j][2] + c1.x + b0;
            vv[3] = acc[j][3] + c1.y + b1;
            #pragma unroll
            for (int rr = 0; rr < 2; rr++) {
                const int row = rBase + rr * 8;
                if (row < NN) {
                    float v0 = vv[rr * 2], v1 = vv[rr * 2 + 1];
                    if (last) {
                        *(float2*)(outf + (size_t)row * DD + col) =
                            make_float2(v0, v1);
                    } else {
                        v0 = fmaxf(v0, 0.f); v1 = fmaxf(v1, 0.f);
                        uint2 o;
                        o.x = packsplit(v0);
                        o.y = packsplit(v1);
                        *(uint2*)(outp + (size_t)row * DD + col) = o;
                    }
                }
            }
        }
    }
}

// ---------------- host driver (graph-capturable) ----------------------------
extern "C" void kernel_launch(void* const* d_in, const int* in_sizes, int n_in,
                              void* d_out, int out_size) {
    const float* x  = (const float*)d_in[0];
    const float* Wl = (const float*)d_in[1];
    const float* Wr = (const float*)d_in[2];
    const float* b  = (const float*)d_in[3];
    const int* ei   = (const int*)d_in[4];
    const int* src  = ei;
    const int* dst  = ei + NE;

    uint32_t *pa, *pb, *pagg;
    unsigned short* wt;
    cudaGetSymbolAddress((void**)&pa, g_pa);
    cudaGetSymbolAddress((void**)&pb, g_pb);
    cudaGetSymbolAddress((void**)&pagg, g_pagg);
    cudaGetSymbolAddress((void**)&wt, g_WT);

    cudaFuncSetAttribute(k_gemm_tc, cudaFuncAttributeMaxDynamicSharedMemorySize, SMEM_TOT);

    const int NB_SCAN = (NN + SCAN_B - 1) / SCAN_B;

    // k_split also zeroes g_cnt/g_fill (must precede k_hist; same stream)
    k_split<<<(NN * DD / 4 + 255) / 256, 256>>>(x, pa);
    k_hist<<<(NE + 255) / 256, 256>>>(dst);
    k_scan1<<<NB_SCAN, SCAN_B>>>();
    k_scan2<<<1, 128>>>(NB_SCAN);
    k_scan3<<<(NN + 255) / 256, 256>>>();
    k_scatter<<<(NE + 255) / 256, 256>>>(src, dst);
    k_wprep<<<(NL * 256 * DD + 255) / 256, 256>>>(Wl, Wr);

    uint32_t *cur = pa, *nxt = pb;
    for (int i = 0; i < NL; i++) {
        k_agg<<<(NN + 7) / 8, 256>>>(cur, pagg);
        int last = (i == NL - 1) ? 1 : 0;
        k_gemm_tc<<<152, 512, SMEM_TOT>>>(pagg, cur,
                                          wt + (size_t)i * 69632,
                                          b + (size_t)i * DD,
                                          nxt, (float*)d_out, last);
        uint32_t* t = cur; cur = nxt; nxt = t;
    }
}

// round 17
// speedup vs baseline: 1.8353x; 1.4890x over previous
#include <cuda_runtime.h>
#include <cuda_fp16.h>
#include <cstdint>

#define NN 100000
#define NE 625000
#define DD 128
#define NL 10

// ---------------- scratch (device globals; no allocation allowed) ----------
// packed activations: one uint32 per element = fp16 hi | fp16 lo<<16
static __device__ uint32_t g_pa[(size_t)NN * DD];    // ping
static __device__ uint32_t g_pb[(size_t)NN * DD];    // pong
static __device__ uint32_t g_pagg[(size_t)NN * DD];  // aggregated
// pre-split W smem image: per layer [2 planes][256 k][136 cols (272B rows)]
static __device__ __align__(16) unsigned short g_WT[(size_t)NL * 69632];
static __device__ float g_invdeg[NN];
static __device__ int   g_cnt[NN];
static __device__ int   g_fill[NN];
static __device__ int   g_rowptr[NN + 1];
static __device__ int   g_csr[NE];
static __device__ int   g_bsums[128];

// ---------------- PTX helpers ----------------------------------------------
__device__ __forceinline__ uint32_t smem_u32(const void* p) {
    uint32_t a;
    asm("{ .reg .u64 t; cvta.to.shared.u64 t, %1; cvt.u32.u64 %0, t; }"
        : "=r"(a) : "l"(p));
    return a;
}
__device__ __forceinline__ void ldsm_x4(uint32_t* r, uint32_t addr) {
    asm volatile("ldmatrix.sync.aligned.m8n8.x4.shared.b16 {%0,%1,%2,%3}, [%4];"
                 : "=r"(r[0]), "=r"(r[1]), "=r"(r[2]), "=r"(r[3]) : "r"(addr));
}
__device__ __forceinline__ void ldsm_x4t(uint32_t* r, uint32_t addr) {
    asm volatile("ldmatrix.sync.aligned.m8n8.x4.trans.shared.b16 {%0,%1,%2,%3}, [%4];"
                 : "=r"(r[0]), "=r"(r[1]), "=r"(r[2]), "=r"(r[3]) : "r"(addr));
}
// main product: fp16 inputs, fp32 accumulate
__device__ __forceinline__ void mma_f32(float* d, const uint32_t* a,
                                        uint32_t b0, uint32_t b1) {
    asm volatile(
        "mma.sync.aligned.m16n8k16.row.col.f32.f16.f16.f32 "
        "{%0,%1,%2,%3}, {%4,%5,%6,%7}, {%8,%9}, {%0,%1,%2,%3};"
        : "+f"(d[0]), "+f"(d[1]), "+f"(d[2]), "+f"(d[3])
        : "r"(a[0]), "r"(a[1]), "r"(a[2]), "r"(a[3]), "r"(b0), "r"(b1));
}
// correction products: fp16 inputs, fp16 accumulate (2x rate on most HMMA impls)
__device__ __forceinline__ void mma_f16(uint32_t* d, const uint32_t* a,
                                        uint32_t b0, uint32_t b1) {
    asm volatile(
        "mma.sync.aligned.m16n8k16.row.col.f16.f16.f16.f16 "
        "{%0,%1}, {%2,%3,%4,%5}, {%6,%7}, {%0,%1};"
        : "+r"(d[0]), "+r"(d[1])
        : "r"(a[0]), "r"(a[1]), "r"(a[2]), "r"(a[3]), "r"(b0), "r"(b1));
}

// ---------------- CSR construction -----------------------------------------
__global__ void k_zero(void) {
    int i = blockIdx.x * blockDim.x + threadIdx.x;
    if (i < NN) { g_cnt[i] = 0; g_fill[i] = 0; }
}
__global__ void k_hist(const int* __restrict__ dst) {
    int e = blockIdx.x * blockDim.x + threadIdx.x;
    if (e < NE) atomicAdd(&g_cnt[dst[e]], 1);
}
#define SCAN_B 1024
__global__ void k_scan1(void) {
    __shared__ int sh[SCAN_B];
    int i = blockIdx.x * SCAN_B + threadIdx.x;
    int v = (i < NN) ? g_cnt[i] : 0;
    sh[threadIdx.x] = v;
    __syncthreads();
    for (int off = 1; off < SCAN_B; off <<= 1) {
        int t = (threadIdx.x >= off) ? sh[threadIdx.x - off] : 0;
        __syncthreads();
        sh[threadIdx.x] += t;
        __syncthreads();
    }
    if (i < NN) g_rowptr[i] = sh[threadIdx.x] - v;
    if (threadIdx.x == SCAN_B - 1) g_bsums[blockIdx.x] = sh[threadIdx.x];
}
__global__ void k_scan2(int nb) {
    __shared__ int sh[128];
    int v = (threadIdx.x < nb) ? g_bsums[threadIdx.x] : 0;
    sh[threadIdx.x] = v;
    __syncthreads();
    for (int off = 1; off < 128; off <<= 1) {
        int t = (threadIdx.x >= off) ? sh[threadIdx.x - off] : 0;
        __syncthreads();
        sh[threadIdx.x] += t;
        __syncthreads();
    }
    if (threadIdx.x < nb) g_bsums[threadIdx.x] = sh[threadIdx.x] - v;  // exclusive
}
__global__ void k_scan3(void) {
    int i = blockIdx.x * blockDim.x + threadIdx.x;
    if (i < NN) {
        g_rowptr[i] += g_bsums[i / SCAN_B];
        int c = g_cnt[i];
        g_invdeg[i] = 1.0f / (float)(c > 0 ? c : 1);
    }
    if (i == 0) g_rowptr[NN] = NE;
}
__global__ void k_scatter(const int* __restrict__ src, const int* __restrict__ dst) {
    int e = blockIdx.x * blockDim.x + threadIdx.x;
    if (e >= NE) return;
    int d = dst[e];
    int pos = atomicAdd(&g_fill[d], 1);
    g_csr[g_rowptr[d] + pos] = src[e];
}

// ---------------- fp32 <-> packed split-fp16 --------------------------------
__device__ __forceinline__ uint32_t packsplit(float v) {
    __half hb = __float2half_rn(v);
    float r = v - __half2float(hb);
    __half lb = __float2half_rn(r);
    return (uint32_t)__half_as_ushort(hb) |
           ((uint32_t)__half_as_ushort(lb) << 16);
}
__device__ __forceinline__ float unpacksum(uint32_t p) {
    float2 f = __half22float2(*(__half2*)&p);
    return f.x + f.y;
}

__global__ void k_split(const float* __restrict__ x, uint32_t* __restrict__ xp) {
    size_t i = ((size_t)blockIdx.x * blockDim.x + threadIdx.x) * 4;
    if (i >= (size_t)NN * DD) return;
    float4 v = *(const float4*)(x + i);
    uint4 o;
    o.x = packsplit(v.x); o.y = packsplit(v.y);
    o.z = packsplit(v.z); o.w = packsplit(v.w);
    *(uint4*)(xp + i) = o;
}

// ---------------- W pre-split into smem image layout ------------------------
__global__ void k_wprep(const float* __restrict__ Wl, const float* __restrict__ Wr) {
    int idx = blockIdx.x * blockDim.x + threadIdx.x;
    if (idx >= NL * 256 * DD) return;
    int l = idx >> 15;
    int rem = idx & 32767;
    int k = rem >> 7;
    int n = rem & 127;
    float w = (k < 128) ? Wl[(size_t)l * 16384 + (size_t)k * 128 + n]
                        : Wr[(size_t)l * 16384 + (size_t)(k - 128) * 128 + n];
    uint32_t p = packsplit(w);
    size_t base = (size_t)l * 69632 + (size_t)k * 136 + n;
    g_WT[base] = (unsigned short)(p & 0xFFFF);
    g_WT[base + 34816] = (unsigned short)(p >> 16);
}

// ---------------- mean aggregation (gather, packed) -------------------------
__global__ void k_agg(const uint32_t* __restrict__ xp, uint32_t* __restrict__ ap) {
    int node = blockIdx.x * 8 + (threadIdx.x >> 5);
    if (node >= NN) return;
    int lane = threadIdx.x & 31;
    int beg = g_rowptr[node];
    int end = g_rowptr[node + 1];
    float4 acc = make_float4(0.f, 0.f, 0.f, 0.f);
    int t = beg;
    for (; t + 1 < end; t += 2) {
        int s0 = g_csr[t], s1 = g_csr[t + 1];
        uint4 v0 = *(const uint4*)(xp + (size_t)s0 * DD + lane * 4);
        uint4 v1 = *(const uint4*)(xp + (size_t)s1 * DD + lane * 4);
        acc.x += unpacksum(v0.x) + unpacksum(v1.x);
        acc.y += unpacksum(v0.y) + unpacksum(v1.y);
        acc.z += unpacksum(v0.z) + unpacksum(v1.z);
        acc.w += unpacksum(v0.w) + unpacksum(v1.w);
    }
    if (t < end) {
        int s0 = g_csr[t];
        uint4 v0 = *(const uint4*)(xp + (size_t)s0 * DD + lane * 4);
        acc.x += unpacksum(v0.x); acc.y += unpacksum(v0.y);
        acc.z += unpacksum(v0.z); acc.w += unpacksum(v0.w);
    }
    float sc = g_invdeg[node];
    uint4 o;
    o.x = packsplit(acc.x * sc); o.y = packsplit(acc.y * sc);
    o.z = packsplit(acc.z * sc); o.w = packsplit(acc.w * sc);
    *(uint4*)(ap + (size_t)node * DD + lane * 4) = o;
}

// ---------------- persistent mma.sync GEMM (512 thr, M=64 tiles) ------------
// Y = [agg|x] @ [Wl;Wr] + b, split-fp16:
//   main AhWh (f32 acc) + corrections AlWh, AhWl (f16 acc).
// Warp tile 16x32 (4x4 warp grid over 64x128 block tile).
#define SMEM_W    0
#define W_PLANE   69632
#define SMEM_A    139264
#define A_BUF     9216           // one plane buffer: 64 rows * 144B
#define A_PAIR    18432          // hi+lo pair
#define SMEM_BIAS 176128
#define SMEM_TOT  176640

__global__ __launch_bounds__(512, 1)
void k_gemm_tc(const uint32_t* __restrict__ aggp,
               const uint32_t* __restrict__ curp,
               const unsigned short* __restrict__ wt,
               const float* __restrict__ bias,
               uint32_t* __restrict__ outp,
               float* __restrict__ outf, int last) {
    extern __shared__ char smem[];
    const uint32_t sb = smem_u32(smem);
    const int tid = threadIdx.x;
    const int wid = tid >> 5, lane = tid & 31;
    const int warp_m = wid & 3, warp_n = wid >> 2;   // 4x4

    {   // load W smem image (139264 B = 8704 uint4) + bias
        const uint4* s4 = (const uint4*)wt;
        uint4* d4 = (uint4*)(smem + SMEM_W);
        #pragma unroll
        for (int i = 0; i < 17; i++) d4[tid + i * 512] = s4[tid + i * 512];
        if (tid < 128) ((float*)(smem + SMEM_BIAS))[tid] = bias[tid];
    }
    __syncthreads();

    // ldmatrix bases
    const uint32_t aBase = sb + SMEM_A +
        (uint32_t)(warp_m * 16 + (lane & 15)) * 144 + (uint32_t)(lane >> 4) * 16;
    const uint32_t bBase = sb + SMEM_W +
        (uint32_t)(lane & 15) * 272 +
        (uint32_t)(warp_n * 32 + (lane >> 4) * 8) * 2;

    // loader coords: row = tid/8 (0..63), 8-col slab = (tid&7)*8
    const int ldRow = tid >> 3;
    const int ldC = (tid & 7) * 8;
    const uint32_t stsH = sb + SMEM_A + (uint32_t)ldRow * 144 + (uint32_t)ldC * 2;

    const int nTiles = (NN + 63) / 64;   // 1563
    uint4 pf[2];

    // prologue prefetch: tile(blockIdx), chunk 0 (agg cols 0..63)
    {
        int row = blockIdx.x * 64 + ldRow;
        if ((int)blockIdx.x < nTiles && row < NN) {
            const uint4* p = (const uint4*)(aggp + (size_t)row * DD + ldC);
            pf[0] = p[0]; pf[1] = p[1];
        } else {
            pf[0] = make_uint4(0, 0, 0, 0);
            pf[1] = make_uint4(0, 0, 0, 0);
        }
    }

    for (int tile = blockIdx.x; tile < nTiles; tile += (int)gridDim.x) {
        const int rowBase = tile * 64;
        float acc[4][4];
        uint32_t accC[4][2];
        #pragma unroll
        for (int i = 0; i < 4; i++) {
            #pragma unroll
            for (int j = 0; j < 4; j++) acc[i][j] = 0.f;
            accC[i][0] = 0u; accC[i][1] = 0u;
        }

        #pragma unroll 1
        for (int c = 0; c < 4; c++) {
            const int b = c & 1;
            // split prefetched packed chunk into hi/lo plane buffers
            {
                const uint32_t dH = stsH + (uint32_t)b * A_PAIR;
                const uint32_t dL = dH + A_BUF;
                uint4 q0 = pf[0], q1 = pf[1];
                uint4 hi, lo;
                hi.x = __byte_perm(q0.x, q0.y, 0x5410);
                hi.y = __byte_perm(q0.z, q0.w, 0x5410);
                hi.z = __byte_perm(q1.x, q1.y, 0x5410);
                hi.w = __byte_perm(q1.z, q1.w, 0x5410);
                lo.x = __byte_perm(q0.x, q0.y, 0x7632);
                lo.y = __byte_perm(q0.z, q0.w, 0x7632);
                lo.z = __byte_perm(q1.x, q1.y, 0x7632);
                lo.w = __byte_perm(q1.z, q1.w, 0x7632);
                asm volatile("st.shared.v4.b32 [%0], {%1,%2,%3,%4};"
                             :: "r"(dH), "r"(hi.x), "r"(hi.y), "r"(hi.z), "r"(hi.w) : "memory");
                asm volatile("st.shared.v4.b32 [%0], {%1,%2,%3,%4};"
                             :: "r"(dL), "r"(lo.x), "r"(lo.y), "r"(lo.z), "r"(lo.w) : "memory");
            }
            // prefetch next chunk (or next tile's chunk 0)
            {
                int nt = tile, nc = c + 1;
                if (nc == 4) { nt = tile + (int)gridDim.x; nc = 0; }
                if (nt < nTiles) {
                    const uint32_t* src = (nc < 2) ? aggp : curp;
                    int row = nt * 64 + ldRow;
                    if (row < NN) {
                        const uint4* p = (const uint4*)(src + (size_t)row * DD +
                                                        (nc & 1) * 64 + ldC);
                        pf[0] = p[0]; pf[1] = p[1];
                    } else {
                        pf[0] = make_uint4(0, 0, 0, 0);
                        pf[1] = make_uint4(0, 0, 0, 0);
                    }
                }
            }
            __syncthreads();

            // compute: main (f32 acc) + corrections (f16 acc)
            const uint32_t aH = aBase + (uint32_t)b * A_PAIR;
            const uint32_t aL = aH + A_BUF;
            const uint32_t wH = bBase + (uint32_t)c * 64 * 272;
            const uint32_t wL = wH + W_PLANE;
            #pragma unroll
            for (int ks = 0; ks < 4; ks++) {
                uint32_t wf[2][4];
                #pragma unroll
                for (int nb = 0; nb < 2; nb++)
                    ldsm_x4t(wf[nb], wH + (uint32_t)ks * 4352 + (uint32_t)nb * 32);
                uint32_t ah[4];
                ldsm_x4(ah, aH + (uint32_t)ks * 32);
                #pragma unroll
                for (int nb = 0; nb < 2; nb++) {
                    mma_f32(acc[nb * 2],     ah, wf[nb][0], wf[nb][1]);
                    mma_f32(acc[nb * 2 + 1], ah, wf[nb][2], wf[nb][3]);
                }
                uint32_t al[4];
                ldsm_x4(al, aL + (uint32_t)ks * 32);
                #pragma unroll
                for (int nb = 0; nb < 2; nb++) {
                    mma_f16(accC[nb * 2],     al, wf[nb][0], wf[nb][1]);
                    mma_f16(accC[nb * 2 + 1], al, wf[nb][2], wf[nb][3]);
                }
                uint32_t wg[2][4];
                #pragma unroll
                for (int nb = 0; nb < 2; nb++)
                    ldsm_x4t(wg[nb], wL + (uint32_t)ks * 4352 + (uint32_t)nb * 32);
                #pragma unroll
                for (int nb = 0; nb < 2; nb++) {
                    mma_f16(accC[nb * 2],     ah, wg[nb][0], wg[nb][1]);
                    mma_f16(accC[nb * 2 + 1], ah, wg[nb][2], wg[nb][3]);
                }
            }
        }

        // ---- epilogue: merge corrections, bias (+relu), store ----
        const float* bs = (const float*)(smem + SMEM_BIAS);
        const int colBase = warp_n * 32 + (lane & 3) * 2;
        const int rBase = rowBase + warp_m * 16 + (lane >> 2);
        #pragma unroll
        for (int j = 0; j < 4; j++) {
            const int col = colBase + j * 8;
            const float b0 = bs[col], b1 = bs[col + 1];
            float2 c0 = __half22float2(*(__half2*)&accC[j][0]); // (r,c),(r,c+1)
            float2 c1 = __half22float2(*(__half2*)&accC[j][1]); // (r+8,c),(r+8,c+1)
            float vv[4];
            vv[0] = acc[j][0] + c0.x + b0;
            vv[1] = acc[j][1] + c0.y + b1;
            vv[2] = acc[j][2] + c1.x + b0;
            vv[3] = acc[j][3] + c1.y + b1;
            #pragma unroll
            for (int rr = 0; rr < 2; rr++) {
                const int row = rBase + rr * 8;
                if (row < NN) {
                    float v0 = vv[rr * 2], v1 = vv[rr * 2 + 1];
                    if (last) {
                        *(float2*)(outf + (size_t)row * DD + col) =
                            make_float2(v0, v1);
                    } else {
                        v0 = fmaxf(v0, 0.f); v1 = fmaxf(v1, 0.f);
                        uint2 o;
                        o.x = packsplit(v0);
                        o.y = packsplit(v1);
                        *(uint2*)(outp + (size_t)row * DD + col) = o;
                    }
                }
            }
        }
    }
}

// ---------------- host driver (graph-capturable) ----------------------------
extern "C" void kernel_launch(void* const* d_in, const int* in_sizes, int n_in,
                              void* d_out, int out_size) {
    const float* x  = (const float*)d_in[0];
    const float* Wl = (const float*)d_in[1];
    const float* Wr = (const float*)d_in[2];
    const float* b  = (const float*)d_in[3];
    const int* ei   = (const int*)d_in[4];
    const int* src  = ei;
    const int* dst  = ei + NE;

    uint32_t *pa, *pb, *pagg;
    unsigned short* wt;
    cudaGetSymbolAddress((void**)&pa, g_pa);
    cudaGetSymbolAddress((void**)&pb, g_pb);
    cudaGetSymbolAddress((void**)&pagg, g_pagg);
    cudaGetSymbolAddress((void**)&wt, g_WT);

    cudaFuncSetAttribute(k_gemm_tc, cudaFuncAttributeMaxDynamicSharedMemorySize, SMEM_TOT);

    const int NB_SCAN = (NN + SCAN_B - 1) / SCAN_B;

    k_zero<<<(NN + 255) / 256, 256>>>();
    k_hist<<<(NE + 255) / 256, 256>>>(dst);
    k_scan1<<<NB_SCAN, SCAN_B>>>();
    k_scan2<<<1, 128>>>(NB_SCAN);
    k_scan3<<<(NN + 255) / 256, 256>>>();
    k_scatter<<<(NE + 255) / 256, 256>>>(src, dst);
    k_split<<<(NN * DD / 4 + 255) / 256, 256>>>(x, pa);
    k_wprep<<<(NL * 256 * DD + 255) / 256, 256>>>(Wl, Wr);

    uint32_t *cur = pa, *nxt = pb;
    for (int i = 0; i < NL; i++) {
        k_agg<<<(NN + 7) / 8, 256>>>(cur, pagg);
        int last = (i == NL - 1) ? 1 : 0;
        k_gemm_tc<<<152, 512, SMEM_TOT>>>(pagg, cur,
                                          wt + (size_t)i * 69632,
                                          b + (size_t)i * DD,
                                          nxt, (float*)d_out, last);
        uint32_t* t = cur; cur = nxt; nxt = t;
    }
}